// round 15
// baseline (speedup 1.0000x reference)
#include <cuda_runtime.h>

// ---------------------------------------------------------------------------
// Shapes fixed by the dataset: N=131072 nodes, S=32, E=2M edges, B=4096
// ---------------------------------------------------------------------------
#define MAXN 131072
#define MAXE (2 * 1024 * 1024)
#define MAXB 4096
#define NBLK 512                      // N / 256

// Scratch (static device globals)
__device__ float g_pi[MAXN * 16];     // per-node pi(16) + b1
__device__ float g_pj[MAXN * 16];     // per-node pj(16)  (gather table)
__device__ float g_hacc[MAXN * 32];   // conv output (pre-BN)
__device__ float g_h[MAXN * 32];      // final activations (dense input)
__device__ int   g_deg[MAXN];         // in-degree per node
__device__ int   g_rowptr[MAXN];      // CSR row start
__device__ int   g_slot[MAXE];        // per-edge slot within its dst row
__device__ int   g_col[MAXE];         // src BYTE offsets (src*64), grouped by dst
__device__ float g_stats[3 * 64];     // per-conv: 32 sums + 32 sumsqs
__device__ float g_t1[MAXB * 256];
__device__ float g_t2[MAXB * 256];

// ---------------------------------------------------------------------------
// deg: degree histogram; records each edge's slot within its dst row
// ---------------------------------------------------------------------------
__global__ void deg_kernel(const int* __restrict__ dst, int E) {
    int i = blockIdx.x * blockDim.x + threadIdx.x;
    int e = i * 4;
    if (e + 3 < E) {
        int4 d = *reinterpret_cast<const int4*>(dst + e);
        int4 sl;
        sl.x = atomicAdd(&g_deg[d.x], 1);
        sl.y = atomicAdd(&g_deg[d.y], 1);
        sl.z = atomicAdd(&g_deg[d.z], 1);
        sl.w = atomicAdd(&g_deg[d.w], 1);
        *reinterpret_cast<int4*>(g_slot + e) = sl;
    } else {
        for (; e < E; e++) g_slot[e] = atomicAdd(&g_deg[dst[e]], 1);
    }
}

// ---------------------------------------------------------------------------
// rowptr + conv1 pi/pj prep + stats zeroing (grid NBLK, block 256)
// ---------------------------------------------------------------------------
__global__ void rowptr_prep_kernel(const float* __restrict__ x,
                                   const float* __restrict__ W1,
                                   const float* __restrict__ b1v) {
    __shared__ int sh[256];
    __shared__ int ws[8];
    __shared__ float sWd[32], sWb[32], sB1[16];
    int t = threadIdx.x;
    int b = blockIdx.x;
    int n = b * 256 + t;

    // global offset: sum of degrees of all nodes before this chunk
    int pre = 0;
    {
        int nq = b * 64;
        const int4* p = reinterpret_cast<const int4*>(g_deg);
        for (int i = t; i < nq; i += 256) {
            int4 v = p[i];
            pre += v.x + v.y + v.z + v.w;
        }
#pragma unroll
        for (int o = 16; o; o >>= 1) pre += __shfl_xor_sync(0xffffffffu, pre, o);
        if ((t & 31) == 0) ws[t >> 5] = pre;
    }

    if (t < 32) {
        sWd[t] = W1[t] - W1[32 + t];
        sWb[t] = W1[32 + t];
    }
    if (t >= 32 && t < 48) sB1[t - 32] = b1v[t - 32];
    if (b == 0 && t >= 48 && t < 240) g_stats[t - 48] = 0.0f;

    int d = g_deg[n];
    sh[t] = d;
    __syncthreads();
    int soff = ws[0] + ws[1] + ws[2] + ws[3] + ws[4] + ws[5] + ws[6] + ws[7];
    for (int o = 1; o < 256; o <<= 1) {
        int u = (t >= o) ? sh[t - o] : 0;
        __syncthreads();
        sh[t] += u;
        __syncthreads();
    }
    g_rowptr[n] = soff + sh[t] - d;

    // conv1 prep: F=2
    float2 xv = reinterpret_cast<const float2*>(x)[n];
    float pi[16], pj[16];
#pragma unroll
    for (int j = 0; j < 16; j++) {
        pi[j] = sB1[j] + fmaf(xv.x, sWd[j], xv.y * sWd[16 + j]);
        pj[j] = fmaf(xv.x, sWb[j], xv.y * sWb[16 + j]);
    }
    float4* opi = reinterpret_cast<float4*>(g_pi + (size_t)n * 16);
    float4* opj = reinterpret_cast<float4*>(g_pj + (size_t)n * 16);
#pragma unroll
    for (int q = 0; q < 4; q++) {
        opi[q] = make_float4(pi[q * 4], pi[q * 4 + 1], pi[q * 4 + 2], pi[q * 4 + 3]);
        opj[q] = make_float4(pj[q * 4], pj[q * 4 + 1], pj[q * 4 + 2], pj[q * 4 + 3]);
    }
}

// fill: atomic-free scatter; stores src BYTE offsets (src*64) for the conv
__global__ void fill_kernel(const int* __restrict__ src,
                            const int* __restrict__ dst, int E) {
    int i = blockIdx.x * blockDim.x + threadIdx.x;
    int e = i * 4;
    if (e + 3 < E) {
        int4 s = *reinterpret_cast<const int4*>(src + e);
        int4 d = *reinterpret_cast<const int4*>(dst + e);
        int4 sl = *reinterpret_cast<const int4*>(g_slot + e);
        g_col[__ldg(g_rowptr + d.x) + sl.x] = s.x << 6;
        g_col[__ldg(g_rowptr + d.y) + sl.y] = s.y << 6;
        g_col[__ldg(g_rowptr + d.z) + sl.z] = s.z << 6;
        g_col[__ldg(g_rowptr + d.w) + sl.w] = s.w << 6;
    } else {
        for (; e < E; e++) g_col[g_rowptr[dst[e]] + g_slot[e]] = src[e] << 6;
    }
}

// ---------------------------------------------------------------------------
// csr_conv: gather-only conv. 16 lanes per node, 4 neighbor slots; gather
// loop batched x4 (four independent gathers in flight per dependency step).
// col holds byte offsets so each gather is base+off.
// Launch: grid = N/64, block 256.
// ---------------------------------------------------------------------------
__global__ void __launch_bounds__(256, 6)
csr_conv_kernel(const float* __restrict__ W2,
                const float* __restrict__ b2v,
                float* __restrict__ stats, int N) {
    __shared__ float sW2[512];
    __shared__ float sB2[32];
    __shared__ float bsum[32], bsq[32];
    int t = threadIdx.x;
    for (int i = t; i < 512; i += 256) sW2[i] = W2[i];
    if (t < 32) {
        sB2[t] = b2v[t];
        bsum[t] = 0.0f;
        bsq[t] = 0.0f;
    }
    __syncthreads();

    int gidx = t >> 4;          // node group in block (0..15)
    int lane16 = t & 15;
    int slot = lane16 >> 2;     // neighbor slot (0..3)
    int q = lane16 & 3;         // quarter (0..3)
    int j = lane16;             // output channel (and j+16)
    int wbase = (t & 31) & ~15;
    const char* pjq = reinterpret_cast<const char*>(g_pj) + q * 16;

    float ssa = 0.0f, ssb = 0.0f, sqa = 0.0f, sqb = 0.0f;

#pragma unroll
    for (int rep = 0; rep < 4; rep++) {
        int n = blockIdx.x * 64 + rep * 16 + gidx;

        float4 u = *reinterpret_cast<const float4*>(g_pi + (size_t)n * 16 + q * 4);
        int rp = g_rowptr[n];
        int dg = g_deg[n];
        const int* cp = g_col + rp;

        float4 acc = make_float4(0.0f, 0.0f, 0.0f, 0.0f);
        int i = slot;
        // 4-deep batch: all four gathers independent -> MLP=4
        for (; i + 12 < dg; i += 16) {
            int o0 = __ldg(cp + i);
            int o1 = __ldg(cp + i + 4);
            int o2 = __ldg(cp + i + 8);
            int o3 = __ldg(cp + i + 12);
            float4 v0 = *reinterpret_cast<const float4*>(pjq + o0);
            float4 v1 = *reinterpret_cast<const float4*>(pjq + o1);
            float4 v2 = *reinterpret_cast<const float4*>(pjq + o2);
            float4 v3 = *reinterpret_cast<const float4*>(pjq + o3);
            acc.x += fmaxf(u.x + v0.x, 0.0f) + fmaxf(u.x + v1.x, 0.0f) +
                     fmaxf(u.x + v2.x, 0.0f) + fmaxf(u.x + v3.x, 0.0f);
            acc.y += fmaxf(u.y + v0.y, 0.0f) + fmaxf(u.y + v1.y, 0.0f) +
                     fmaxf(u.y + v2.y, 0.0f) + fmaxf(u.y + v3.y, 0.0f);
            acc.z += fmaxf(u.z + v0.z, 0.0f) + fmaxf(u.z + v1.z, 0.0f) +
                     fmaxf(u.z + v2.z, 0.0f) + fmaxf(u.z + v3.z, 0.0f);
            acc.w += fmaxf(u.w + v0.w, 0.0f) + fmaxf(u.w + v1.w, 0.0f) +
                     fmaxf(u.w + v2.w, 0.0f) + fmaxf(u.w + v3.w, 0.0f);
        }
        // 2-deep tail
        for (; i + 4 < dg; i += 8) {
            int o0 = __ldg(cp + i);
            int o1 = __ldg(cp + i + 4);
            float4 v0 = *reinterpret_cast<const float4*>(pjq + o0);
            float4 v1 = *reinterpret_cast<const float4*>(pjq + o1);
            acc.x += fmaxf(u.x + v0.x, 0.0f) + fmaxf(u.x + v1.x, 0.0f);
            acc.y += fmaxf(u.y + v0.y, 0.0f) + fmaxf(u.y + v1.y, 0.0f);
            acc.z += fmaxf(u.z + v0.z, 0.0f) + fmaxf(u.z + v1.z, 0.0f);
            acc.w += fmaxf(u.w + v0.w, 0.0f) + fmaxf(u.w + v1.w, 0.0f);
        }
        if (i < dg) {
            int o0 = __ldg(cp + i);
            float4 v = *reinterpret_cast<const float4*>(pjq + o0);
            acc.x += fmaxf(u.x + v.x, 0.0f);
            acc.y += fmaxf(u.y + v.y, 0.0f);
            acc.z += fmaxf(u.z + v.z, 0.0f);
            acc.w += fmaxf(u.w + v.w, 0.0f);
        }

#pragma unroll
        for (int off = 4; off <= 8; off <<= 1) {
            acc.x += __shfl_xor_sync(0xffffffffu, acc.x, off);
            acc.y += __shfl_xor_sync(0xffffffffu, acc.y, off);
            acc.z += __shfl_xor_sync(0xffffffffu, acc.z, off);
            acc.w += __shfl_xor_sync(0xffffffffu, acc.w, off);
        }

        float h[16];
#pragma unroll
        for (int k = 0; k < 16; k++) {
            float comp = (k & 3) == 0 ? acc.x : (k & 3) == 1 ? acc.y
                       : (k & 3) == 2 ? acc.z : acc.w;
            h[k] = __shfl_sync(0xffffffffu, comp, wbase | (k >> 2), 32);
        }

        float dgf = (float)dg;
        float oa = dgf * sB2[j];
        float ob = dgf * sB2[j + 16];
#pragma unroll
        for (int k = 0; k < 16; k++) {
            oa = fmaf(h[k], sW2[k * 32 + j], oa);
            ob = fmaf(h[k], sW2[k * 32 + j + 16], ob);
        }
        g_hacc[(size_t)n * 32 + j] = oa;
        g_hacc[(size_t)n * 32 + 16 + j] = ob;

        ssa += oa;
        sqa += oa * oa;
        ssb += ob;
        sqb += ob * ob;
    }

    ssa += __shfl_xor_sync(0xffffffffu, ssa, 16);
    ssb += __shfl_xor_sync(0xffffffffu, ssb, 16);
    sqa += __shfl_xor_sync(0xffffffffu, sqa, 16);
    sqb += __shfl_xor_sync(0xffffffffu, sqb, 16);
    if ((t & 31) < 16) {
        atomicAdd(&bsum[j], ssa);
        atomicAdd(&bsq[j], sqa);
        atomicAdd(&bsum[j + 16], ssb);
        atomicAdd(&bsq[j + 16], sqb);
    }
    __syncthreads();
    if (t < 32)
        atomicAdd(&stats[t], bsum[t]);
    else if (t < 64)
        atomicAdd(&stats[t], bsq[t - 32]);
}

// ---------------------------------------------------------------------------
// BN apply + ReLU, fused with next conv's pi/pj precompute (or final write).
// ---------------------------------------------------------------------------
template <bool FINAL>
__global__ void bn_prep_kernel(const float* __restrict__ gamma,
                               const float* __restrict__ beta,
                               const float* __restrict__ W1next,
                               const float* __restrict__ b1next,
                               const float* __restrict__ stats, int N) {
    __shared__ float sc[32], sh[32];
    __shared__ float sWd[512], sWb[512], sB1[16];
    if (threadIdx.x < 32) {
        int c = threadIdx.x;
        float invn = 1.0f / (float)N;
        float mu = stats[c] * invn;
        float var = stats[32 + c] * invn - mu * mu;
        float s = rsqrtf(var + 1e-5f) * gamma[c];
        sc[c] = s;
        sh[c] = beta[c] - mu * s;
    }
    if (!FINAL) {
        for (int i = threadIdx.x; i < 512; i += blockDim.x) {
            float wb = W1next[512 + i];
            sWd[i] = W1next[i] - wb;
            sWb[i] = wb;
        }
        if (threadIdx.x >= 32 && threadIdx.x < 48)
            sB1[threadIdx.x - 32] = b1next[threadIdx.x - 32];
    }
    __syncthreads();
    int n = blockIdx.x * blockDim.x + threadIdx.x;
    if (n >= N) return;

    float hn[32];
    const float4* ip = reinterpret_cast<const float4*>(g_hacc + (size_t)n * 32);
#pragma unroll
    for (int qq = 0; qq < 8; qq++) {
        float4 v = ip[qq];
        hn[qq * 4 + 0] = fmaxf(fmaf(v.x, sc[qq * 4 + 0], sh[qq * 4 + 0]), 0.0f);
        hn[qq * 4 + 1] = fmaxf(fmaf(v.y, sc[qq * 4 + 1], sh[qq * 4 + 1]), 0.0f);
        hn[qq * 4 + 2] = fmaxf(fmaf(v.z, sc[qq * 4 + 2], sh[qq * 4 + 2]), 0.0f);
        hn[qq * 4 + 3] = fmaxf(fmaf(v.w, sc[qq * 4 + 3], sh[qq * 4 + 3]), 0.0f);
    }
    if (FINAL) {
        float4* op = reinterpret_cast<float4*>(g_h + (size_t)n * 32);
#pragma unroll
        for (int qq = 0; qq < 8; qq++)
            op[qq] = make_float4(hn[qq * 4], hn[qq * 4 + 1], hn[qq * 4 + 2], hn[qq * 4 + 3]);
    } else {
        float pi[16], pj[16];
#pragma unroll
        for (int jj = 0; jj < 16; jj++) { pi[jj] = sB1[jj]; pj[jj] = 0.0f; }
#pragma unroll
        for (int k = 0; k < 32; k++) {
            float v = hn[k];
#pragma unroll
            for (int jj = 0; jj < 16; jj++) {
                pi[jj] = fmaf(v, sWd[k * 16 + jj], pi[jj]);
                pj[jj] = fmaf(v, sWb[k * 16 + jj], pj[jj]);
            }
        }
        float4* opi = reinterpret_cast<float4*>(g_pi + (size_t)n * 16);
        float4* opj = reinterpret_cast<float4*>(g_pj + (size_t)n * 16);
#pragma unroll
        for (int qq = 0; qq < 4; qq++) {
            opi[qq] = make_float4(pi[qq * 4], pi[qq * 4 + 1], pi[qq * 4 + 2], pi[qq * 4 + 3]);
            opj[qq] = make_float4(pj[qq * 4], pj[qq * 4 + 1], pj[qq * 4 + 2], pj[qq * 4 + 3]);
        }
    }
}

// ---------------------------------------------------------------------------
// Double-buffered fp32 GEMM: C[M,N] = act(A @ B + bias)
// 128x64 tile, BK=16, 512 threads, 4x4 micro-tile, 1 sync/iter.
// K and N compile-time.
// ---------------------------------------------------------------------------
template <bool RELU, int K, int N>
__global__ void gemm512_kernel(const float* __restrict__ A,
                               const float* __restrict__ Bm,
                               const float* __restrict__ bias,
                               float* __restrict__ C, int M) {
    const int BM = 128, BN = 64, BK = 16;
    __shared__ float As[2][BK][BM + 4];
    __shared__ float Bs[2][BK][BN];
    int tid = threadIdx.x;
    int tx = tid & 15;
    int ty = tid >> 4;
    int bm = blockIdx.y * BM;
    int bn = blockIdx.x * BN;

    int ar = tid >> 2;
    int ac4 = (tid & 3) * 4;
    int br = tid >> 4;
    int bc4 = (tid & 15) * 4;
    const float* Aptr = A + (size_t)(bm + ar) * K + ac4;
    const float* Bptr = Bm + (size_t)br * N + bn + bc4;

    {
        float4 v = *reinterpret_cast<const float4*>(Aptr);
        As[0][ac4 + 0][ar] = v.x;
        As[0][ac4 + 1][ar] = v.y;
        As[0][ac4 + 2][ar] = v.z;
        As[0][ac4 + 3][ar] = v.w;
        if (tid < 256)
            *reinterpret_cast<float4*>(&Bs[0][br][bc4]) =
                *reinterpret_cast<const float4*>(Bptr);
    }
    __syncthreads();

    float acc[4][4];
#pragma unroll
    for (int u = 0; u < 4; u++)
#pragma unroll
        for (int v = 0; v < 4; v++) acc[u][v] = 0.0f;

    const int nk = K / BK;
#pragma unroll 4
    for (int kt = 0; kt < nk; kt++) {
        int p = kt & 1;
        float4 na, nb;
        bool more = (kt + 1 < nk);
        if (more) {
            na = *reinterpret_cast<const float4*>(Aptr + (size_t)(kt + 1) * BK);
            if (tid < 256)
                nb = *reinterpret_cast<const float4*>(Bptr + (size_t)(kt + 1) * BK * N);
        }
#pragma unroll
        for (int k = 0; k < BK; k++) {
            float4 b = *reinterpret_cast<const float4*>(&Bs[p][k][tx * 4]);
            float4 a = *reinterpret_cast<const float4*>(&As[p][k][ty * 4]);
            float av[4] = {a.x, a.y, a.z, a.w};
            float bv[4] = {b.x, b.y, b.z, b.w};
#pragma unroll
            for (int u = 0; u < 4; u++)
#pragma unroll
                for (int v = 0; v < 4; v++)
                    acc[u][v] = fmaf(av[u], bv[v], acc[u][v]);
        }
        if (more) {
            As[1 - p][ac4 + 0][ar] = na.x;
            As[1 - p][ac4 + 1][ar] = na.y;
            As[1 - p][ac4 + 2][ar] = na.z;
            As[1 - p][ac4 + 3][ar] = na.w;
            if (tid < 256)
                *reinterpret_cast<float4*>(&Bs[1 - p][br][bc4]) = nb;
        }
        __syncthreads();
    }
    float4 bb = *reinterpret_cast<const float4*>(bias + bn + tx * 4);
#pragma unroll
    for (int u = 0; u < 4; u++) {
        int row = bm + ty * 4 + u;
        float4 r;
        r.x = acc[u][0] + bb.x;
        r.y = acc[u][1] + bb.y;
        r.z = acc[u][2] + bb.z;
        r.w = acc[u][3] + bb.w;
        if (RELU) {
            r.x = fmaxf(r.x, 0.0f);
            r.y = fmaxf(r.y, 0.0f);
            r.z = fmaxf(r.z, 0.0f);
            r.w = fmaxf(r.w, 0.0f);
        }
        *reinterpret_cast<float4*>(C + (size_t)row * N + bn + tx * 4) = r;
    }
}

// ---------------------------------------------------------------------------
// advq: fused adv GEMM (aW remap) + value head + dueling combine -> q
// BM=32 rows/block -> grid 128 blocks. 256 threads, 2x4 micro-tile.
// ---------------------------------------------------------------------------
template <int K>
__global__ void advq_kernel(const float* __restrict__ A,
                            const float* __restrict__ aW,
                            const float* __restrict__ ab,
                            const float* __restrict__ vW,
                            const float* __restrict__ vb,
                            float* __restrict__ q, int M) {
    const int BM = 32, BK = 16;
    __shared__ float As[BK][BM + 4];
    __shared__ float Bs[BK][64];
    __shared__ float svW[K];
    __shared__ float sAB[64];
    __shared__ float svb;
    int tid = threadIdx.x;
    int tx = tid & 15;
    int ty = tid >> 4;
    int bm = blockIdx.x * BM;

    if (tid < K) svW[tid] = vW[tid];
    if (tid < 64) sAB[tid] = ab[tid];
    if (tid == 64) svb = vb[0];

    float acc[2][4] = {{0, 0, 0, 0}, {0, 0, 0, 0}};
    float vacc[2] = {0.0f, 0.0f};

#pragma unroll 2
    for (int k0 = 0; k0 < K; k0 += BK) {
        if (tid < 128) {
            int r = tid >> 2;
            int c4 = (tid & 3) * 4;
            float4 v = *reinterpret_cast<const float4*>(
                A + (size_t)(bm + r) * K + k0 + c4);
            As[c4 + 0][r] = v.x;
            As[c4 + 1][r] = v.y;
            As[c4 + 2][r] = v.z;
            As[c4 + 3][r] = v.w;
        }
#pragma unroll
        for (int qq = 0; qq < 4; qq++) {
            int i = tid + qq * 256;
            int r = i >> 6, c = i & 63;
            Bs[r][c] = aW[(c >> 1) * 512 + (k0 + r) * 2 + (c & 1)];
        }
        __syncthreads();
#pragma unroll
        for (int k = 0; k < BK; k++) {
            float4 b = *reinterpret_cast<const float4*>(&Bs[k][tx * 4]);
            float a0 = As[k][ty * 2];
            float a1 = As[k][ty * 2 + 1];
            float wv = svW[k0 + k];
            vacc[0] = fmaf(a0, wv, vacc[0]);
            vacc[1] = fmaf(a1, wv, vacc[1]);
            float bv[4] = {b.x, b.y, b.z, b.w};
#pragma unroll
            for (int v = 0; v < 4; v++) {
                acc[0][v] = fmaf(a0, bv[v], acc[0][v]);
                acc[1][v] = fmaf(a1, bv[v], acc[1][v]);
            }
        }
        __syncthreads();
    }
    int c0 = tx * 4;
    float ab0 = sAB[c0], ab1 = sAB[c0 + 1], ab2 = sAB[c0 + 2], ab3 = sAB[c0 + 3];
#pragma unroll
    for (int u = 0; u < 2; u++) {
        int row = bm + ty * 2 + u;
        float value = vacc[u] + svb;
        float a0 = acc[u][0] + ab0;
        float a1 = acc[u][1] + ab1;
        float a2 = acc[u][2] + ab2;
        float a3 = acc[u][3] + ab3;
        float4 r;
        r.x = value + 0.5f * (a0 - a1);
        r.y = value + 0.5f * (a1 - a0);
        r.z = value + 0.5f * (a2 - a3);
        r.w = value + 0.5f * (a3 - a2);
        *reinterpret_cast<float4*>(q + (size_t)row * 64 + c0) = r;
    }
}

// ---------------------------------------------------------------------------
extern "C" void kernel_launch(void* const* d_in, const int* in_sizes, int n_in,
                              void* d_out, int out_size) {
    const float* x    = (const float*)d_in[0];
    const int*   ei   = (const int*)d_in[1];
    const float* c1W1 = (const float*)d_in[2];
    const float* c1b1 = (const float*)d_in[3];
    const float* c1W2 = (const float*)d_in[4];
    const float* c1b2 = (const float*)d_in[5];
    const float* c2W1 = (const float*)d_in[6];
    const float* c2b1 = (const float*)d_in[7];
    const float* c2W2 = (const float*)d_in[8];
    const float* c2b2 = (const float*)d_in[9];
    const float* c3W1 = (const float*)d_in[10];
    const float* c3b1 = (const float*)d_in[11];
    const float* c3W2 = (const float*)d_in[12];
    const float* c3b2 = (const float*)d_in[13];
    const float* bn_g = (const float*)d_in[14];
    const float* bn_b = (const float*)d_in[15];
    const float* mW1  = (const float*)d_in[16];
    const float* mb1  = (const float*)d_in[17];
    const float* mW2  = (const float*)d_in[18];
    const float* mb2  = (const float*)d_in[19];
    const float* mW3  = (const float*)d_in[20];
    const float* mb3  = (const float*)d_in[21];
    const float* vW   = (const float*)d_in[22];
    const float* vb   = (const float*)d_in[23];
    const float* aW   = (const float*)d_in[24];
    const float* ab   = (const float*)d_in[25];

    int N = in_sizes[0] / 2;
    int E = in_sizes[1] / 2;
    int B = N / 32;
    const int* src = ei;
    const int* dstp = ei + E;

    float *h, *stats, *t1, *t2;
    int* deg;
    cudaGetSymbolAddress((void**)&h, g_h);
    cudaGetSymbolAddress((void**)&stats, g_stats);
    cudaGetSymbolAddress((void**)&t1, g_t1);
    cudaGetSymbolAddress((void**)&t2, g_t2);
    cudaGetSymbolAddress((void**)&deg, g_deg);

    const int TPB = 256;
    int nblocks = N / TPB;              // 512
    int e4blocks = (E / 4 + TPB - 1) / TPB;

    cudaMemsetAsync(deg, 0, (size_t)N * sizeof(int), 0);

    // CSR build + conv1 prep: (1) deg (2) rowptr+prep (3) fill
    deg_kernel<<<e4blocks, TPB>>>(dstp, E);
    rowptr_prep_kernel<<<nblocks, TPB>>>(x, c1W1, c1b1);
    fill_kernel<<<e4blocks, TPB>>>(src, dstp, E);

    const float* W2s[3] = {c1W2, c2W2, c3W2};
    const float* b2s[3] = {c1b2, c2b2, c3b2};
    const float* W1next[3] = {c2W1, c3W1, c3W1};
    const float* b1next[3] = {c2b1, c3b1, c3b1};

    for (int c = 0; c < 3; c++) {
        // (4) csr_conv for c==0 -> profiled launch
        csr_conv_kernel<<<N / 64, TPB>>>(W2s[c], b2s[c], stats + c * 64, N);
        if (c < 2)
            bn_prep_kernel<false><<<nblocks, TPB>>>(bn_g + c * 32, bn_b + c * 32,
                                                    W1next[c], b1next[c],
                                                    stats + c * 64, N);
        else
            bn_prep_kernel<true><<<nblocks, TPB>>>(bn_g + 64, bn_b + 64, c3W1,
                                                   c3b1, stats + c * 64, N);
    }

    // ---- dense head: g_h is [B, 1024] row-major ----
    dim3 g1(256 / 64, B / 128);
    gemm512_kernel<true, 1024, 256><<<g1, 512>>>(h, mW1, mb1, t1, B);
    gemm512_kernel<true, 256, 256><<<g1, 512>>>(t1, mW2, mb2, t2, B);
    gemm512_kernel<true, 256, 256><<<g1, 512>>>(t2, mW3, mb3, t1, B);

    // fused adv GEMM + value + dueling combine -> d_out (128 blocks)
    advq_kernel<256><<<B / 32, 256>>>(t1, aW, ab, vW, vb, (float*)d_out, B);
}

// round 16
// speedup vs baseline: 1.0010x; 1.0010x over previous
#include <cuda_runtime.h>

// ---------------------------------------------------------------------------
// Shapes fixed by the dataset: N=131072 nodes, S=32, E=2M edges, B=4096
// ---------------------------------------------------------------------------
#define MAXN 131072
#define MAXE (2 * 1024 * 1024)
#define MAXB 4096
#define NBLK 512                      // N / 256

// Scratch (static device globals)
__device__ float g_pi[MAXN * 16];     // per-node pi(16) + b1
__device__ float g_pj[MAXN * 16];     // per-node pj(16)  (gather table)
__device__ float g_hacc[MAXN * 32];   // conv output (pre-BN)
__device__ float g_h[MAXN * 32];      // final activations (dense input)
__device__ int   g_deg[MAXN];         // in-degree per node
__device__ int   g_rowptr[MAXN];      // CSR row start
__device__ int   g_slot[MAXE];        // per-edge slot within its dst row
__device__ int   g_col[MAXE];         // src BYTE offsets (src*64), grouped by dst
__device__ float g_stats[3 * 64];     // per-conv: 32 sums + 32 sumsqs
__device__ float g_t1[MAXB * 256];
__device__ float g_t2[MAXB * 256];

// ---------------------------------------------------------------------------
// deg: degree histogram; records each edge's slot within its dst row
// ---------------------------------------------------------------------------
__global__ void deg_kernel(const int* __restrict__ dst, int E) {
    int i = blockIdx.x * blockDim.x + threadIdx.x;
    int e = i * 4;
    if (e + 3 < E) {
        int4 d = *reinterpret_cast<const int4*>(dst + e);
        int4 sl;
        sl.x = atomicAdd(&g_deg[d.x], 1);
        sl.y = atomicAdd(&g_deg[d.y], 1);
        sl.z = atomicAdd(&g_deg[d.z], 1);
        sl.w = atomicAdd(&g_deg[d.w], 1);
        *reinterpret_cast<int4*>(g_slot + e) = sl;
    } else {
        for (; e < E; e++) g_slot[e] = atomicAdd(&g_deg[dst[e]], 1);
    }
}

// ---------------------------------------------------------------------------
// rowptr + conv1 pi/pj prep + stats zeroing (grid NBLK, block 256)
// ---------------------------------------------------------------------------
__global__ void rowptr_prep_kernel(const float* __restrict__ x,
                                   const float* __restrict__ W1,
                                   const float* __restrict__ b1v) {
    __shared__ int sh[256];
    __shared__ int ws[8];
    __shared__ float sWd[32], sWb[32], sB1[16];
    int t = threadIdx.x;
    int b = blockIdx.x;
    int n = b * 256 + t;

    // global offset: sum of degrees of all nodes before this chunk
    int pre = 0;
    {
        int nq = b * 64;
        const int4* p = reinterpret_cast<const int4*>(g_deg);
        for (int i = t; i < nq; i += 256) {
            int4 v = p[i];
            pre += v.x + v.y + v.z + v.w;
        }
#pragma unroll
        for (int o = 16; o; o >>= 1) pre += __shfl_xor_sync(0xffffffffu, pre, o);
        if ((t & 31) == 0) ws[t >> 5] = pre;
    }

    if (t < 32) {
        sWd[t] = W1[t] - W1[32 + t];
        sWb[t] = W1[32 + t];
    }
    if (t >= 32 && t < 48) sB1[t - 32] = b1v[t - 32];
    if (b == 0 && t >= 48 && t < 240) g_stats[t - 48] = 0.0f;

    int d = g_deg[n];
    sh[t] = d;
    __syncthreads();
    int soff = ws[0] + ws[1] + ws[2] + ws[3] + ws[4] + ws[5] + ws[6] + ws[7];
    for (int o = 1; o < 256; o <<= 1) {
        int u = (t >= o) ? sh[t - o] : 0;
        __syncthreads();
        sh[t] += u;
        __syncthreads();
    }
    g_rowptr[n] = soff + sh[t] - d;

    // conv1 prep: F=2
    float2 xv = reinterpret_cast<const float2*>(x)[n];
    float pi[16], pj[16];
#pragma unroll
    for (int j = 0; j < 16; j++) {
        pi[j] = sB1[j] + fmaf(xv.x, sWd[j], xv.y * sWd[16 + j]);
        pj[j] = fmaf(xv.x, sWb[j], xv.y * sWb[16 + j]);
    }
    float4* opi = reinterpret_cast<float4*>(g_pi + (size_t)n * 16);
    float4* opj = reinterpret_cast<float4*>(g_pj + (size_t)n * 16);
#pragma unroll
    for (int q = 0; q < 4; q++) {
        opi[q] = make_float4(pi[q * 4], pi[q * 4 + 1], pi[q * 4 + 2], pi[q * 4 + 3]);
        opj[q] = make_float4(pj[q * 4], pj[q * 4 + 1], pj[q * 4 + 2], pj[q * 4 + 3]);
    }
}

// fill: atomic-free scatter; stores src BYTE offsets (src*64) for the conv
__global__ void fill_kernel(const int* __restrict__ src,
                            const int* __restrict__ dst, int E) {
    int i = blockIdx.x * blockDim.x + threadIdx.x;
    int e = i * 4;
    if (e + 3 < E) {
        int4 s = *reinterpret_cast<const int4*>(src + e);
        int4 d = *reinterpret_cast<const int4*>(dst + e);
        int4 sl = *reinterpret_cast<const int4*>(g_slot + e);
        g_col[__ldg(g_rowptr + d.x) + sl.x] = s.x << 6;
        g_col[__ldg(g_rowptr + d.y) + sl.y] = s.y << 6;
        g_col[__ldg(g_rowptr + d.z) + sl.z] = s.z << 6;
        g_col[__ldg(g_rowptr + d.w) + sl.w] = s.w << 6;
    } else {
        for (; e < E; e++) g_col[g_rowptr[dst[e]] + g_slot[e]] = src[e] << 6;
    }
}

// ---------------------------------------------------------------------------
// csr_conv: gather-only conv. 16 lanes per node, 4 neighbor slots; gather
// loop unrolled x2; h[16] distributed via smem staging (1 STS + 4 LDS per
// lane) instead of 16 shfl broadcasts.
// Launch: grid = N/64, block 256.
// ---------------------------------------------------------------------------
__global__ void __launch_bounds__(256, 6)
csr_conv_kernel(const float* __restrict__ W2,
                const float* __restrict__ b2v,
                float* __restrict__ stats, int N) {
    __shared__ float sW2[512];
    __shared__ float sB2[32];
    __shared__ float bsum[32], bsq[32];
    __shared__ float sH[8][2][16];     // [warp][node-half][h16]
    int t = threadIdx.x;
    for (int i = t; i < 512; i += 256) sW2[i] = W2[i];
    if (t < 32) {
        sB2[t] = b2v[t];
        bsum[t] = 0.0f;
        bsq[t] = 0.0f;
    }
    __syncthreads();

    int gidx = t >> 4;          // node group in block (0..15)
    int lane16 = t & 15;
    int slot = lane16 >> 2;     // neighbor slot (0..3)
    int q = lane16 & 3;         // quarter (0..3)
    int j = lane16;             // output channel (and j+16)
    int wid = t >> 5;           // warp id (0..7)
    int nh = (t >> 4) & 1;      // node half within warp
    const char* pjq = reinterpret_cast<const char*>(g_pj) + q * 16;

    float ssa = 0.0f, ssb = 0.0f, sqa = 0.0f, sqb = 0.0f;

#pragma unroll
    for (int rep = 0; rep < 4; rep++) {
        int n = blockIdx.x * 64 + rep * 16 + gidx;

        float4 u = *reinterpret_cast<const float4*>(g_pi + (size_t)n * 16 + q * 4);
        int rp = g_rowptr[n];
        int dg = g_deg[n];
        const int* cp = g_col + rp;

        float4 acc = make_float4(0.0f, 0.0f, 0.0f, 0.0f);
        int i = slot;
        for (; i + 4 < dg; i += 8) {
            int o0 = __ldg(cp + i);
            int o1 = __ldg(cp + i + 4);
            float4 v0 = *reinterpret_cast<const float4*>(pjq + o0);
            float4 v1 = *reinterpret_cast<const float4*>(pjq + o1);
            acc.x += fmaxf(u.x + v0.x, 0.0f) + fmaxf(u.x + v1.x, 0.0f);
            acc.y += fmaxf(u.y + v0.y, 0.0f) + fmaxf(u.y + v1.y, 0.0f);
            acc.z += fmaxf(u.z + v0.z, 0.0f) + fmaxf(u.z + v1.z, 0.0f);
            acc.w += fmaxf(u.w + v0.w, 0.0f) + fmaxf(u.w + v1.w, 0.0f);
        }
        if (i < dg) {
            int o0 = __ldg(cp + i);
            float4 v = *reinterpret_cast<const float4*>(pjq + o0);
            acc.x += fmaxf(u.x + v.x, 0.0f);
            acc.y += fmaxf(u.y + v.y, 0.0f);
            acc.z += fmaxf(u.z + v.z, 0.0f);
            acc.w += fmaxf(u.w + v.w, 0.0f);
        }

        // reduce over the 4 neighbor slots
#pragma unroll
        for (int off = 4; off <= 8; off <<= 1) {
            acc.x += __shfl_xor_sync(0xffffffffu, acc.x, off);
            acc.y += __shfl_xor_sync(0xffffffffu, acc.y, off);
            acc.z += __shfl_xor_sync(0xffffffffu, acc.z, off);
            acc.w += __shfl_xor_sync(0xffffffffu, acc.w, off);
        }

        // stage h[16] via smem: slot-0 lanes store their quarter
        if (slot == 0)
            *reinterpret_cast<float4*>(&sH[wid][nh][q * 4]) =
                make_float4(acc.x, acc.y, acc.z, acc.w);
        __syncwarp();
        float h[16];
        {
            const float4* hp = reinterpret_cast<const float4*>(sH[wid][nh]);
            float4 h0 = hp[0], h1 = hp[1], h2 = hp[2], h3 = hp[3];
            h[0] = h0.x; h[1] = h0.y; h[2] = h0.z; h[3] = h0.w;
            h[4] = h1.x; h[5] = h1.y; h[6] = h1.z; h[7] = h1.w;
            h[8] = h2.x; h[9] = h2.y; h[10] = h2.z; h[11] = h2.w;
            h[12] = h3.x; h[13] = h3.y; h[14] = h3.z; h[15] = h3.w;
        }
        __syncwarp();

        float dgf = (float)dg;
        float oa = dgf * sB2[j];
        float ob = dgf * sB2[j + 16];
#pragma unroll
        for (int k = 0; k < 16; k++) {
            oa = fmaf(h[k], sW2[k * 32 + j], oa);
            ob = fmaf(h[k], sW2[k * 32 + j + 16], ob);
        }
        g_hacc[(size_t)n * 32 + j] = oa;
        g_hacc[(size_t)n * 32 + 16 + j] = ob;

        ssa += oa;
        sqa += oa * oa;
        ssb += ob;
        sqb += ob * ob;
    }

    ssa += __shfl_xor_sync(0xffffffffu, ssa, 16);
    ssb += __shfl_xor_sync(0xffffffffu, ssb, 16);
    sqa += __shfl_xor_sync(0xffffffffu, sqa, 16);
    sqb += __shfl_xor_sync(0xffffffffu, sqb, 16);
    if ((t & 31) < 16) {
        atomicAdd(&bsum[j], ssa);
        atomicAdd(&bsq[j], sqa);
        atomicAdd(&bsum[j + 16], ssb);
        atomicAdd(&bsq[j + 16], sqb);
    }
    __syncthreads();
    if (t < 32)
        atomicAdd(&stats[t], bsum[t]);
    else if (t < 64)
        atomicAdd(&stats[t], bsq[t - 32]);
}

// ---------------------------------------------------------------------------
// BN apply + ReLU, fused with next conv's pi/pj precompute (or final write).
// ---------------------------------------------------------------------------
template <bool FINAL>
__global__ void bn_prep_kernel(const float* __restrict__ gamma,
                               const float* __restrict__ beta,
                               const float* __restrict__ W1next,
                               const float* __restrict__ b1next,
                               const float* __restrict__ stats, int N) {
    __shared__ float sc[32], sh[32];
    __shared__ float sWd[512], sWb[512], sB1[16];
    if (threadIdx.x < 32) {
        int c = threadIdx.x;
        float invn = 1.0f / (float)N;
        float mu = stats[c] * invn;
        float var = stats[32 + c] * invn - mu * mu;
        float s = rsqrtf(var + 1e-5f) * gamma[c];
        sc[c] = s;
        sh[c] = beta[c] - mu * s;
    }
    if (!FINAL) {
        for (int i = threadIdx.x; i < 512; i += blockDim.x) {
            float wb = W1next[512 + i];
            sWd[i] = W1next[i] - wb;
            sWb[i] = wb;
        }
        if (threadIdx.x >= 32 && threadIdx.x < 48)
            sB1[threadIdx.x - 32] = b1next[threadIdx.x - 32];
    }
    __syncthreads();
    int n = blockIdx.x * blockDim.x + threadIdx.x;
    if (n >= N) return;

    float hn[32];
    const float4* ip = reinterpret_cast<const float4*>(g_hacc + (size_t)n * 32);
#pragma unroll
    for (int qq = 0; qq < 8; qq++) {
        float4 v = ip[qq];
        hn[qq * 4 + 0] = fmaxf(fmaf(v.x, sc[qq * 4 + 0], sh[qq * 4 + 0]), 0.0f);
        hn[qq * 4 + 1] = fmaxf(fmaf(v.y, sc[qq * 4 + 1], sh[qq * 4 + 1]), 0.0f);
        hn[qq * 4 + 2] = fmaxf(fmaf(v.z, sc[qq * 4 + 2], sh[qq * 4 + 2]), 0.0f);
        hn[qq * 4 + 3] = fmaxf(fmaf(v.w, sc[qq * 4 + 3], sh[qq * 4 + 3]), 0.0f);
    }
    if (FINAL) {
        float4* op = reinterpret_cast<float4*>(g_h + (size_t)n * 32);
#pragma unroll
        for (int qq = 0; qq < 8; qq++)
            op[qq] = make_float4(hn[qq * 4], hn[qq * 4 + 1], hn[qq * 4 + 2], hn[qq * 4 + 3]);
    } else {
        float pi[16], pj[16];
#pragma unroll
        for (int jj = 0; jj < 16; jj++) { pi[jj] = sB1[jj]; pj[jj] = 0.0f; }
#pragma unroll
        for (int k = 0; k < 32; k++) {
            float v = hn[k];
#pragma unroll
            for (int jj = 0; jj < 16; jj++) {
                pi[jj] = fmaf(v, sWd[k * 16 + jj], pi[jj]);
                pj[jj] = fmaf(v, sWb[k * 16 + jj], pj[jj]);
            }
        }
        float4* opi = reinterpret_cast<float4*>(g_pi + (size_t)n * 16);
        float4* opj = reinterpret_cast<float4*>(g_pj + (size_t)n * 16);
#pragma unroll
        for (int qq = 0; qq < 4; qq++) {
            opi[qq] = make_float4(pi[qq * 4], pi[qq * 4 + 1], pi[qq * 4 + 2], pi[qq * 4 + 3]);
            opj[qq] = make_float4(pj[qq * 4], pj[qq * 4 + 1], pj[qq * 4 + 2], pj[qq * 4 + 3]);
        }
    }
}

// ---------------------------------------------------------------------------
// Double-buffered fp32 GEMM: C[M,N] = act(A @ B + bias)
// 128x64 tile, BK=16, 512 threads, 4x4 micro-tile, 1 sync/iter.
// K and N compile-time.
// ---------------------------------------------------------------------------
template <bool RELU, int K, int N>
__global__ void gemm512_kernel(const float* __restrict__ A,
                               const float* __restrict__ Bm,
                               const float* __restrict__ bias,
                               float* __restrict__ C, int M) {
    const int BM = 128, BN = 64, BK = 16;
    __shared__ float As[2][BK][BM + 4];
    __shared__ float Bs[2][BK][BN];
    int tid = threadIdx.x;
    int tx = tid & 15;
    int ty = tid >> 4;
    int bm = blockIdx.y * BM;
    int bn = blockIdx.x * BN;

    int ar = tid >> 2;
    int ac4 = (tid & 3) * 4;
    int br = tid >> 4;
    int bc4 = (tid & 15) * 4;
    const float* Aptr = A + (size_t)(bm + ar) * K + ac4;
    const float* Bptr = Bm + (size_t)br * N + bn + bc4;

    {
        float4 v = *reinterpret_cast<const float4*>(Aptr);
        As[0][ac4 + 0][ar] = v.x;
        As[0][ac4 + 1][ar] = v.y;
        As[0][ac4 + 2][ar] = v.z;
        As[0][ac4 + 3][ar] = v.w;
        if (tid < 256)
            *reinterpret_cast<float4*>(&Bs[0][br][bc4]) =
                *reinterpret_cast<const float4*>(Bptr);
    }
    __syncthreads();

    float acc[4][4];
#pragma unroll
    for (int u = 0; u < 4; u++)
#pragma unroll
        for (int v = 0; v < 4; v++) acc[u][v] = 0.0f;

    const int nk = K / BK;
#pragma unroll 4
    for (int kt = 0; kt < nk; kt++) {
        int p = kt & 1;
        float4 na, nb;
        bool more = (kt + 1 < nk);
        if (more) {
            na = *reinterpret_cast<const float4*>(Aptr + (size_t)(kt + 1) * BK);
            if (tid < 256)
                nb = *reinterpret_cast<const float4*>(Bptr + (size_t)(kt + 1) * BK * N);
        }
#pragma unroll
        for (int k = 0; k < BK; k++) {
            float4 b = *reinterpret_cast<const float4*>(&Bs[p][k][tx * 4]);
            float4 a = *reinterpret_cast<const float4*>(&As[p][k][ty * 4]);
            float av[4] = {a.x, a.y, a.z, a.w};
            float bv[4] = {b.x, b.y, b.z, b.w};
#pragma unroll
            for (int u = 0; u < 4; u++)
#pragma unroll
                for (int v = 0; v < 4; v++)
                    acc[u][v] = fmaf(av[u], bv[v], acc[u][v]);
        }
        if (more) {
            As[1 - p][ac4 + 0][ar] = na.x;
            As[1 - p][ac4 + 1][ar] = na.y;
            As[1 - p][ac4 + 2][ar] = na.z;
            As[1 - p][ac4 + 3][ar] = na.w;
            if (tid < 256)
                *reinterpret_cast<float4*>(&Bs[1 - p][br][bc4]) = nb;
        }
        __syncthreads();
    }
    float4 bb = *reinterpret_cast<const float4*>(bias + bn + tx * 4);
#pragma unroll
    for (int u = 0; u < 4; u++) {
        int row = bm + ty * 4 + u;
        float4 r;
        r.x = acc[u][0] + bb.x;
        r.y = acc[u][1] + bb.y;
        r.z = acc[u][2] + bb.z;
        r.w = acc[u][3] + bb.w;
        if (RELU) {
            r.x = fmaxf(r.x, 0.0f);
            r.y = fmaxf(r.y, 0.0f);
            r.z = fmaxf(r.z, 0.0f);
            r.w = fmaxf(r.w, 0.0f);
        }
        *reinterpret_cast<float4*>(C + (size_t)row * N + bn + tx * 4) = r;
    }
}

// ---------------------------------------------------------------------------
// advq: fused adv GEMM (aW remap) + value head + dueling combine -> q
// BM=32 rows/block -> grid 128 blocks. 256 threads, 2x4 micro-tile.
// ---------------------------------------------------------------------------
template <int K>
__global__ void advq_kernel(const float* __restrict__ A,
                            const float* __restrict__ aW,
                            const float* __restrict__ ab,
                            const float* __restrict__ vW,
                            const float* __restrict__ vb,
                            float* __restrict__ q, int M) {
    const int BM = 32, BK = 16;
    __shared__ float As[BK][BM + 4];
    __shared__ float Bs[BK][64];
    __shared__ float svW[K];
    __shared__ float sAB[64];
    __shared__ float svb;
    int tid = threadIdx.x;
    int tx = tid & 15;
    int ty = tid >> 4;
    int bm = blockIdx.x * BM;

    if (tid < K) svW[tid] = vW[tid];
    if (tid < 64) sAB[tid] = ab[tid];
    if (tid == 64) svb = vb[0];

    float acc[2][4] = {{0, 0, 0, 0}, {0, 0, 0, 0}};
    float vacc[2] = {0.0f, 0.0f};

#pragma unroll 2
    for (int k0 = 0; k0 < K; k0 += BK) {
        if (tid < 128) {
            int r = tid >> 2;
            int c4 = (tid & 3) * 4;
            float4 v = *reinterpret_cast<const float4*>(
                A + (size_t)(bm + r) * K + k0 + c4);
            As[c4 + 0][r] = v.x;
            As[c4 + 1][r] = v.y;
            As[c4 + 2][r] = v.z;
            As[c4 + 3][r] = v.w;
        }
#pragma unroll
        for (int qq = 0; qq < 4; qq++) {
            int i = tid + qq * 256;
            int r = i >> 6, c = i & 63;
            Bs[r][c] = aW[(c >> 1) * 512 + (k0 + r) * 2 + (c & 1)];
        }
        __syncthreads();
#pragma unroll
        for (int k = 0; k < BK; k++) {
            float4 b = *reinterpret_cast<const float4*>(&Bs[k][tx * 4]);
            float a0 = As[k][ty * 2];
            float a1 = As[k][ty * 2 + 1];
            float wv = svW[k0 + k];
            vacc[0] = fmaf(a0, wv, vacc[0]);
            vacc[1] = fmaf(a1, wv, vacc[1]);
            float bv[4] = {b.x, b.y, b.z, b.w};
#pragma unroll
            for (int v = 0; v < 4; v++) {
                acc[0][v] = fmaf(a0, bv[v], acc[0][v]);
                acc[1][v] = fmaf(a1, bv[v], acc[1][v]);
            }
        }
        __syncthreads();
    }
    int c0 = tx * 4;
    float ab0 = sAB[c0], ab1 = sAB[c0 + 1], ab2 = sAB[c0 + 2], ab3 = sAB[c0 + 3];
#pragma unroll
    for (int u = 0; u < 2; u++) {
        int row = bm + ty * 2 + u;
        float value = vacc[u] + svb;
        float a0 = acc[u][0] + ab0;
        float a1 = acc[u][1] + ab1;
        float a2 = acc[u][2] + ab2;
        float a3 = acc[u][3] + ab3;
        float4 r;
        r.x = value + 0.5f * (a0 - a1);
        r.y = value + 0.5f * (a1 - a0);
        r.z = value + 0.5f * (a2 - a3);
        r.w = value + 0.5f * (a3 - a2);
        *reinterpret_cast<float4*>(q + (size_t)row * 64 + c0) = r;
    }
}

// ---------------------------------------------------------------------------
extern "C" void kernel_launch(void* const* d_in, const int* in_sizes, int n_in,
                              void* d_out, int out_size) {
    const float* x    = (const float*)d_in[0];
    const int*   ei   = (const int*)d_in[1];
    const float* c1W1 = (const float*)d_in[2];
    const float* c1b1 = (const float*)d_in[3];
    const float* c1W2 = (const float*)d_in[4];
    const float* c1b2 = (const float*)d_in[5];
    const float* c2W1 = (const float*)d_in[6];
    const float* c2b1 = (const float*)d_in[7];
    const float* c2W2 = (const float*)d_in[8];
    const float* c2b2 = (const float*)d_in[9];
    const float* c3W1 = (const float*)d_in[10];
    const float* c3b1 = (const float*)d_in[11];
    const float* c3W2 = (const float*)d_in[12];
    const float* c3b2 = (const float*)d_in[13];
    const float* bn_g = (const float*)d_in[14];
    const float* bn_b = (const float*)d_in[15];
    const float* mW1  = (const float*)d_in[16];
    const float* mb1  = (const float*)d_in[17];
    const float* mW2  = (const float*)d_in[18];
    const float* mb2  = (const float*)d_in[19];
    const float* mW3  = (const float*)d_in[20];
    const float* mb3  = (const float*)d_in[21];
    const float* vW   = (const float*)d_in[22];
    const float* vb   = (const float*)d_in[23];
    const float* aW   = (const float*)d_in[24];
    const float* ab   = (const float*)d_in[25];

    int N = in_sizes[0] / 2;
    int E = in_sizes[1] / 2;
    int B = N / 32;
    const int* src = ei;
    const int* dstp = ei + E;

    float *h, *stats, *t1, *t2;
    int* deg;
    cudaGetSymbolAddress((void**)&h, g_h);
    cudaGetSymbolAddress((void**)&stats, g_stats);
    cudaGetSymbolAddress((void**)&t1, g_t1);
    cudaGetSymbolAddress((void**)&t2, g_t2);
    cudaGetSymbolAddress((void**)&deg, g_deg);

    const int TPB = 256;
    int nblocks = N / TPB;              // 512
    int e4blocks = (E / 4 + TPB - 1) / TPB;

    cudaMemsetAsync(deg, 0, (size_t)N * sizeof(int), 0);

    // CSR build + conv1 prep: (1) deg (2) rowptr+prep (3) fill
    deg_kernel<<<e4blocks, TPB>>>(dstp, E);
    rowptr_prep_kernel<<<nblocks, TPB>>>(x, c1W1, c1b1);
    fill_kernel<<<e4blocks, TPB>>>(src, dstp, E);

    const float* W2s[3] = {c1W2, c2W2, c3W2};
    const float* b2s[3] = {c1b2, c2b2, c3b2};
    const float* W1next[3] = {c2W1, c3W1, c3W1};
    const float* b1next[3] = {c2b1, c3b1, c3b1};

    for (int c = 0; c < 3; c++) {
        // (4) csr_conv for c==0 -> profiled launch
        csr_conv_kernel<<<N / 64, TPB>>>(W2s[c], b2s[c], stats + c * 64, N);
        if (c < 2)
            bn_prep_kernel<false><<<nblocks, TPB>>>(bn_g + c * 32, bn_b + c * 32,
                                                    W1next[c], b1next[c],
                                                    stats + c * 64, N);
        else
            bn_prep_kernel<true><<<nblocks, TPB>>>(bn_g + 64, bn_b + 64, c3W1,
                                                   c3b1, stats + c * 64, N);
    }

    // ---- dense head: g_h is [B, 1024] row-major ----
    dim3 g1(256 / 64, B / 128);
    gemm512_kernel<true, 1024, 256><<<g1, 512>>>(h, mW1, mb1, t1, B);
    gemm512_kernel<true, 256, 256><<<g1, 512>>>(t1, mW2, mb2, t2, B);
    gemm512_kernel<true, 256, 256><<<g1, 512>>>(t2, mW3, mb3, t1, B);

    // fused adv GEMM + value + dueling combine -> d_out (128 blocks)
    advq_kernel<256><<<B / 32, 256>>>(t1, aW, ab, vW, vb, (float*)d_out, B);
}